// round 11
// baseline (speedup 1.0000x reference)
#include <cuda_runtime.h>
#include <cuda_fp16.h>
#include <cuda_bf16.h>
#include <math.h>

// Problem dims (fixed by the dataset)
#define NB 4
#define CH 3
#define HH 1080
#define WW 1920
#define HW (HH * WW)
#define NHW (NB * HW)

#define SZ_IN     (NB * 3 * HW)   // 24883200
#define SZ_FLOW   (NB * 2 * HW)   // 16588800
#define SZ_METRIC (NB * 1 * HW)   //  8294400

// Staggered dual accumulator, f16, 4 channels (c0*mw, c1*mw, c2*mw, m*w):
//   A: [N, H, W, 4]      — receives pairs starting at EVEN x0 (cols x0, x0+1)
//   B: [N, H, 1922, 4]   — one-cell-shifted (col index = x+1, padded both
//                          ends) — receives pairs starting at ODD x0.
// Every pixel's footprint row is then ONE 16B v4.f16x2 RED regardless of x0
// parity: 2 RED messages/pixel total (vs 3 avg before). Out-of-image corners
// land in B's padding cells (never read, re-zeroed each pass).
#define BW 1922
#define A_HALVES ((size_t)NB * HH * WW * 4)
#define B_HALVES ((size_t)NB * HH * BW * 4)

__device__ __align__(16) __half g_acc[A_HALVES + B_HALVES];

static __device__ __forceinline__ unsigned pack2(float a, float b) {
    __half2 h = __floats2half2_rn(a, b);
    return *reinterpret_cast<unsigned*>(&h);
}

__global__ void splat_kernel(const float* __restrict__ in,
                             const float* __restrict__ flow,
                             const float* __restrict__ metric) {
    int p = blockIdx.x * blockDim.x + threadIdx.x;
    if (p >= NHW) return;
    int b   = p / HW;
    int rem = p - b * HW;
    int y   = rem / WW;
    int x   = rem - y * WW;

    float fx = flow[(size_t)(b * 2 + 0) * HW + rem];
    float fy = flow[(size_t)(b * 2 + 1) * HW + rem];
    float tx = (float)x + fx;
    float ty = (float)y + fy;
    if (!isfinite(tx) || !isfinite(ty)) return;  // ref zeroes these contributions

    float m  = __expf(metric[p]);
    float v0 = in[(size_t)(b * 3 + 0) * HW + rem] * m;
    float v1 = in[(size_t)(b * 3 + 1) * HW + rem] * m;
    float v2 = in[(size_t)(b * 3 + 2) * HW + rem] * m;

    float fxf = floorf(tx);
    float fyf = floorf(ty);
    int x0 = (int)fxf;
    int y0 = (int)fyf;
    float ax = tx - fxf;
    float ay = ty - fyf;

    float wx0 = 1.f - ax, wx1 = ax;
    float wy_[2] = {1.f - ay, ay};

    // Select target array by x0 parity; compute aligned pair column.
    bool odd = (x0 & 1) != 0;
    // even: pair valid iff x0 in [0, WW-2]; odd: iff x0 in [-1, WW-1]
    bool ok = odd ? (x0 >= -1 && x0 <= WW - 1) : ((unsigned)x0 <= (unsigned)(WW - 2));
    if (!ok) return;

    __half* arr;
    int col, rw;
    if (odd) { arr = g_acc + A_HALVES + (size_t)b * HH * BW * 4; col = x0 + 1; rw = BW; }
    else     { arr = g_acc            + (size_t)b * HH * WW * 4; col = x0;     rw = WW; }

#pragma unroll
    for (int dy = 0; dy < 2; dy++) {
        int iy = y0 + dy;
        if (iy < 0 || iy >= HH) continue;
        float W0 = wx0 * wy_[dy];
        float W1 = wx1 * wy_[dy];
        unsigned a0 = pack2(v0 * W0, v1 * W0);
        unsigned a1 = pack2(v2 * W0, m  * W0);
        unsigned b0 = pack2(v0 * W1, v1 * W1);
        unsigned b1 = pack2(v2 * W1, m  * W1);
        __half* ptr = arr + ((size_t)iy * rw + col) * 4;
        asm volatile(
            "red.global.add.noftz.v4.f16x2 [%0], {%1, %2, %3, %4};"
            :: "l"(ptr), "r"(a0), "r"(a1), "r"(b0), "r"(b1)
            : "memory");
    }
}

// Normalize + re-zero: out = (A[x] + B[x+1]) normalized; both cells zeroed
// in-place so the accumulator is clean for the next launch / graph replay.
__global__ void norm_kernel(float* __restrict__ out) {
    int p = blockIdx.x * blockDim.x + threadIdx.x;
    if (p >= NHW) return;
    int b   = p / HW;
    int rem = p - b * HW;
    int y   = rem / WW;
    int x   = rem - y * WW;

    uint2* aCell = reinterpret_cast<uint2*>(g_acc) + p;
    uint2* bCell = reinterpret_cast<uint2*>(g_acc + A_HALVES) +
                   ((size_t)b * HH + y) * BW + (x + 1);

    uint2 ac = *aCell;  *aCell = make_uint2(0u, 0u);
    uint2 bc = *bCell;  *bCell = make_uint2(0u, 0u);

    // Clear B's padding columns (0 and BW-1) once per row.
    if (x == 0) {
        uint2* rowB = reinterpret_cast<uint2*>(g_acc + A_HALVES) +
                      ((size_t)b * HH + y) * BW;
        rowB[0]      = make_uint2(0u, 0u);
        rowB[BW - 1] = make_uint2(0u, 0u);
    }

    float2 a01 = __half22float2(*reinterpret_cast<__half2*>(&ac.x));
    float2 a23 = __half22float2(*reinterpret_cast<__half2*>(&ac.y));
    float2 b01 = __half22float2(*reinterpret_cast<__half2*>(&bc.x));
    float2 b23 = __half22float2(*reinterpret_cast<__half2*>(&bc.y));

    float den = a23.y + b23.y;
    float inv = 1.0f / (den + 1e-7f);
    out[(size_t)(b * 3 + 0) * HW + rem] = (a01.x + b01.x) * inv;
    out[(size_t)(b * 3 + 1) * HW + rem] = (a01.y + b01.y) * inv;
    out[(size_t)(b * 3 + 2) * HW + rem] = (a23.x + b23.x) * inv;
}

extern "C" void kernel_launch(void* const* d_in, const int* in_sizes, int n_in,
                              void* d_out, int out_size) {
    // Identify inputs by element count — robust to any metadata ordering.
    const float* tenIn     = nullptr;
    const float* tenFlow   = nullptr;
    const float* tenMetric = nullptr;
    for (int i = 0; i < n_in; i++) {
        if      (in_sizes[i] == SZ_IN)     tenIn     = (const float*)d_in[i];
        else if (in_sizes[i] == SZ_FLOW)   tenFlow   = (const float*)d_in[i];
        else if (in_sizes[i] == SZ_METRIC) tenMetric = (const float*)d_in[i];
    }
    float* out = (float*)d_out;

    const int threads = 256;
    const int blocks  = (NHW + threads - 1) / threads;  // 32400

    splat_kernel<<<blocks, threads>>>(tenIn, tenFlow, tenMetric);
    norm_kernel <<<blocks, threads>>>(out);
}

// round 12
// speedup vs baseline: 1.9710x; 1.9710x over previous
#include <cuda_runtime.h>
#include <cuda_fp16.h>
#include <cuda_bf16.h>
#include <math.h>

// Problem dims (fixed by the dataset)
#define NB 4
#define CH 3
#define HH 1080
#define WW 1920
#define HW (HH * WW)
#define NHW (NB * HW)

#define SZ_IN     (NB * 3 * HW)   // 24883200
#define SZ_FLOW   (NB * 2 * HW)   // 16588800
#define SZ_METRIC (NB * 1 * HW)   //  8294400

// Staggered dual accumulator, f16, 4 channels (c0*mw, c1*mw, c2*mw, m*w):
//   A: [N, H, W, 4]      — pairs starting at EVEN x0 (cols x0, x0+1)
//   B: [N, H, 1922, 4]   — shifted by one col (index x+1), pads both ends —
//                          pairs starting at ODD x0 (16B-aligned there).
// Every pixel = one 16B v4.f16x2 RED per footprint row (2 msgs/px).
// Processed batch-by-batch: A_b+B_b = 33 MB stays L2-resident through
// splat_b -> norm_b, so RMWs don't pay DRAM fill/writeback.
#define BW 1922
#define A_HALVES ((size_t)NB * HH * WW * 4)
#define B_HALVES ((size_t)NB * HH * BW * 4)

__device__ __align__(16) __half g_acc[A_HALVES + B_HALVES];

static __device__ __forceinline__ unsigned pack2(float a, float b) {
    __half2 h = __floats2half2_rn(a, b);
    return *reinterpret_cast<unsigned*>(&h);
}

__global__ void splat_kernel(const float* __restrict__ in,
                             const float* __restrict__ flow,
                             const float* __restrict__ metric,
                             int b) {
    int rem = blockIdx.x * blockDim.x + threadIdx.x;
    if (rem >= HW) return;
    int y = rem / WW;
    int x = rem - y * WW;

    float fx = flow[(size_t)(b * 2 + 0) * HW + rem];
    float fy = flow[(size_t)(b * 2 + 1) * HW + rem];
    float tx = (float)x + fx;
    float ty = (float)y + fy;
    if (!isfinite(tx) || !isfinite(ty)) return;  // ref zeroes these contributions

    float m  = __expf(metric[(size_t)b * HW + rem]);
    float v0 = in[(size_t)(b * 3 + 0) * HW + rem] * m;
    float v1 = in[(size_t)(b * 3 + 1) * HW + rem] * m;
    float v2 = in[(size_t)(b * 3 + 2) * HW + rem] * m;

    float fxf = floorf(tx);
    float fyf = floorf(ty);
    int x0 = (int)fxf;
    int y0 = (int)fyf;
    float ax = tx - fxf;
    float ay = ty - fyf;

    float wx0 = 1.f - ax, wx1 = ax;
    float wy_[2] = {1.f - ay, ay};

    bool odd = (x0 & 1) != 0;
    // even: pair valid iff x0 in [0, WW-2]; odd: iff x0 in [-1, WW-1]
    bool ok = odd ? (x0 >= -1 && x0 <= WW - 1) : ((unsigned)x0 <= (unsigned)(WW - 2));
    if (!ok) return;

    __half* arr;
    int col, rw;
    if (odd) { arr = g_acc + A_HALVES + (size_t)b * HH * BW * 4; col = x0 + 1; rw = BW; }
    else     { arr = g_acc            + (size_t)b * HH * WW * 4; col = x0;     rw = WW; }

#pragma unroll
    for (int dy = 0; dy < 2; dy++) {
        int iy = y0 + dy;
        if (iy < 0 || iy >= HH) continue;
        float W0 = wx0 * wy_[dy];
        float W1 = wx1 * wy_[dy];
        unsigned a0 = pack2(v0 * W0, v1 * W0);
        unsigned a1 = pack2(v2 * W0, m  * W0);
        unsigned b0 = pack2(v0 * W1, v1 * W1);
        unsigned b1 = pack2(v2 * W1, m  * W1);
        __half* ptr = arr + ((size_t)iy * rw + col) * 4;
        asm volatile(
            "red.global.add.noftz.v4.f16x2 [%0], {%1, %2, %3, %4};"
            :: "l"(ptr), "r"(a0), "r"(a1), "r"(b0), "r"(b1)
            : "memory");
    }
}

// Fused normalize + re-zero, 2 px/thread, loads batched before stores for MLP.
// out = (A[x] + B[x+1]) normalized. Re-zeroes every A/B cell (incl. B pads),
// restoring the "acc_b == 0" invariant for the next launch / graph replay.
__global__ void norm_kernel(float* __restrict__ out, int b) {
    int t = blockIdx.x * blockDim.x + threadIdx.x;
    if (t >= HW / 2) return;
    int rem = t * 2;          // pixel pair (x, x+1), x even
    int y   = rem / WW;
    int x   = rem - y * WW;

    __half* A_b = g_acc            + (size_t)b * HH * WW * 4;
    __half* B_b = g_acc + A_HALVES + (size_t)b * HH * BW * 4;

    float4* aPtr  = reinterpret_cast<float4*>(A_b + ((size_t)y * WW + x) * 4);
    uint2*  bPtr0 = reinterpret_cast<uint2*>(B_b + ((size_t)y * BW + x + 1) * 4);
    uint2*  bPtr1 = bPtr0 + 1;

    // Independent loads first (MLP=3), then zero-stores, then math.
    float4 av = *aPtr;
    uint2  b0 = *bPtr0;
    uint2  b1 = *bPtr1;

    *aPtr  = make_float4(0.f, 0.f, 0.f, 0.f);
    *bPtr0 = make_uint2(0u, 0u);
    *bPtr1 = make_uint2(0u, 0u);
    if (x == 0) {  // clear B padding cols 0 and BW-1 for this row
        uint2* rowB = reinterpret_cast<uint2*>(B_b + (size_t)y * BW * 4);
        rowB[0]      = make_uint2(0u, 0u);
        rowB[BW - 1] = make_uint2(0u, 0u);
    }

    unsigned au0 = __float_as_uint(av.x), au1 = __float_as_uint(av.y);
    unsigned au2 = __float_as_uint(av.z), au3 = __float_as_uint(av.w);
    float2 aL01 = __half22float2(*reinterpret_cast<__half2*>(&au0));
    float2 aL23 = __half22float2(*reinterpret_cast<__half2*>(&au1));
    float2 aR01 = __half22float2(*reinterpret_cast<__half2*>(&au2));
    float2 aR23 = __half22float2(*reinterpret_cast<__half2*>(&au3));
    float2 bL01 = __half22float2(*reinterpret_cast<__half2*>(&b0.x));
    float2 bL23 = __half22float2(*reinterpret_cast<__half2*>(&b0.y));
    float2 bR01 = __half22float2(*reinterpret_cast<__half2*>(&b1.x));
    float2 bR23 = __half22float2(*reinterpret_cast<__half2*>(&b1.y));

    float invL = 1.0f / ((aL23.y + bL23.y) + 1e-7f);
    float invR = 1.0f / ((aR23.y + bR23.y) + 1e-7f);

    size_t o = (size_t)(b * 3) * HW + rem;
    *reinterpret_cast<float2*>(out + o)          = make_float2((aL01.x + bL01.x) * invL, (aR01.x + bR01.x) * invR);
    *reinterpret_cast<float2*>(out + o + HW)     = make_float2((aL01.y + bL01.y) * invL, (aR01.y + bR01.y) * invR);
    *reinterpret_cast<float2*>(out + o + 2 * HW) = make_float2((aL23.x + bL23.x) * invL, (aR23.x + bR23.x) * invR);
}

extern "C" void kernel_launch(void* const* d_in, const int* in_sizes, int n_in,
                              void* d_out, int out_size) {
    // Identify inputs by element count — robust to any metadata ordering.
    const float* tenIn     = nullptr;
    const float* tenFlow   = nullptr;
    const float* tenMetric = nullptr;
    for (int i = 0; i < n_in; i++) {
        if      (in_sizes[i] == SZ_IN)     tenIn     = (const float*)d_in[i];
        else if (in_sizes[i] == SZ_FLOW)   tenFlow   = (const float*)d_in[i];
        else if (in_sizes[i] == SZ_METRIC) tenMetric = (const float*)d_in[i];
    }
    float* out = (float*)d_out;

    const int threads = 256;
    const int sblocks = (HW + threads - 1) / threads;      // 8100
    const int nblocks = (HW / 2 + threads - 1) / threads;  // 4050

    // Per-batch: splat into L2-resident 33MB slice, then norm (L2-hot reads)
    // + in-place re-zero (replaces all zero passes).
    for (int b = 0; b < NB; b++) {
        splat_kernel<<<sblocks, threads>>>(tenIn, tenFlow, tenMetric, b);
        norm_kernel <<<nblocks, threads>>>(out, b);
    }
}

// round 13
// speedup vs baseline: 3.1393x; 1.5927x over previous
#include <cuda_runtime.h>
#include <cuda_fp16.h>
#include <cuda_bf16.h>
#include <math.h>

// Problem dims (fixed by the dataset)
#define NB 4
#define CH 3
#define HH 1080
#define WW 1920
#define HW (HH * WW)
#define NHW (NB * HW)

#define SZ_IN     (NB * 3 * HW)   // 24883200
#define SZ_FLOW   (NB * 2 * HW)   // 16588800
#define SZ_METRIC (NB * 1 * HW)   //  8294400

// Staggered dual accumulator, f16, 4 channels (c0*mw, c1*mw, c2*mw, m*w):
//   A: [N, H, W, 4]      — pairs starting at EVEN x0 (cols x0, x0+1)
//   B: [N, H, 1922, 4]   — shifted one col (index x+1, pads both ends) —
//                          pairs starting at ODD x0 (16B-aligned there).
// Every pixel = one 16B v4.f16x2 RED per footprint row: 2 msgs/px — the
// message floor for a 32B/px footprint with 16B REDs.
// Batch-sliced: A_b+B_b = 33 MB is L2-resident through zero->splat->norm.
#define BW 1922
#define A_HALVES ((size_t)NB * HH * WW * 4)
#define B_HALVES ((size_t)NB * HH * BW * 4)
#define A_B_HALVES ((size_t)HH * WW * 4)   // per-batch A slice (halves)
#define B_B_HALVES ((size_t)HH * BW * 4)   // per-batch B slice (halves)

__device__ __align__(16) __half g_acc[A_HALVES + B_HALVES];

static __device__ __forceinline__ unsigned pack2(float a, float b) {
    __half2 h = __floats2half2_rn(a, b);
    return *reinterpret_cast<unsigned*>(&h);
}

// Zero batch b's A and B slices (incl. B padding cols). Pure full-line
// 16B stores — measured near peak store bandwidth.
#define ZA16 (A_B_HALVES / 8)              // 16B chunks in A_b
#define ZB16 (B_B_HALVES / 8)              // 16B chunks in B_b
__global__ void zero_kernel(int b) {
    int i = blockIdx.x * blockDim.x + threadIdx.x;
    float4 z = make_float4(0.f, 0.f, 0.f, 0.f);
    if (i < ZA16) {
        reinterpret_cast<float4*>(g_acc + (size_t)b * A_B_HALVES)[i] = z;
    } else if (i < ZA16 + ZB16) {
        reinterpret_cast<float4*>(g_acc + A_HALVES + (size_t)b * B_B_HALVES)[i - ZA16] = z;
    }
}

__global__ void splat_kernel(const float* __restrict__ in,
                             const float* __restrict__ flow,
                             const float* __restrict__ metric,
                             int b) {
    int rem = blockIdx.x * blockDim.x + threadIdx.x;
    if (rem >= HW) return;
    int y = rem / WW;
    int x = rem - y * WW;

    float fx = flow[(size_t)(b * 2 + 0) * HW + rem];
    float fy = flow[(size_t)(b * 2 + 1) * HW + rem];
    float tx = (float)x + fx;
    float ty = (float)y + fy;
    if (!isfinite(tx) || !isfinite(ty)) return;  // ref zeroes these contributions

    float m  = __expf(metric[(size_t)b * HW + rem]);
    float v0 = in[(size_t)(b * 3 + 0) * HW + rem] * m;
    float v1 = in[(size_t)(b * 3 + 1) * HW + rem] * m;
    float v2 = in[(size_t)(b * 3 + 2) * HW + rem] * m;

    float fxf = floorf(tx);
    float fyf = floorf(ty);
    int x0 = (int)fxf;
    int y0 = (int)fyf;
    float ax = tx - fxf;
    float ay = ty - fyf;

    float wx0 = 1.f - ax, wx1 = ax;
    float wy_[2] = {1.f - ay, ay};

    bool odd = (x0 & 1) != 0;
    // even: pair valid iff x0 in [0, WW-2]; odd: iff x0 in [-1, WW-1]
    bool ok = odd ? (x0 >= -1 && x0 <= WW - 1) : ((unsigned)x0 <= (unsigned)(WW - 2));
    if (!ok) return;

    __half* arr;
    int col, rw;
    if (odd) { arr = g_acc + A_HALVES + (size_t)b * B_B_HALVES; col = x0 + 1; rw = BW; }
    else     { arr = g_acc            + (size_t)b * A_B_HALVES; col = x0;     rw = WW; }

#pragma unroll
    for (int dy = 0; dy < 2; dy++) {
        int iy = y0 + dy;
        if (iy < 0 || iy >= HH) continue;
        float W0 = wx0 * wy_[dy];
        float W1 = wx1 * wy_[dy];
        unsigned a0 = pack2(v0 * W0, v1 * W0);
        unsigned a1 = pack2(v2 * W0, m  * W0);
        unsigned b0 = pack2(v0 * W1, v1 * W1);
        unsigned b1 = pack2(v2 * W1, m  * W1);
        __half* ptr = arr + ((size_t)iy * rw + col) * 4;
        asm volatile(
            "red.global.add.noftz.v4.f16x2 [%0], {%1, %2, %3, %4};"
            :: "l"(ptr), "r"(a0), "r"(a1), "r"(b0), "r"(b1)
            : "memory");
    }
}

// Read-only normalize, 2 px/thread: out = (A[x] + B[x+1]) / (den + eps).
// No re-zeroing here (zero_kernel owns that) — pure streaming reads of
// L2-hot accumulator lines + coalesced planar output stores.
__global__ void norm_kernel(float* __restrict__ out, int b) {
    int t = blockIdx.x * blockDim.x + threadIdx.x;
    if (t >= HW / 2) return;
    int rem = t * 2;          // pixel pair (x, x+1), x even
    int y   = rem / WW;
    int x   = rem - y * WW;

    const __half* A_b = g_acc            + (size_t)b * A_B_HALVES;
    const __half* B_b = g_acc + A_HALVES + (size_t)b * B_B_HALVES;

    // A: 16B aligned (x even). B: two 8B cells at odd index x+1.
    float4 av = *reinterpret_cast<const float4*>(A_b + ((size_t)y * WW + x) * 4);
    uint2  b0 = *reinterpret_cast<const uint2*>(B_b + ((size_t)y * BW + x + 1) * 4);
    uint2  b1 = *reinterpret_cast<const uint2*>(B_b + ((size_t)y * BW + x + 2) * 4);

    unsigned au0 = __float_as_uint(av.x), au1 = __float_as_uint(av.y);
    unsigned au2 = __float_as_uint(av.z), au3 = __float_as_uint(av.w);
    float2 aL01 = __half22float2(*reinterpret_cast<__half2*>(&au0));
    float2 aL23 = __half22float2(*reinterpret_cast<__half2*>(&au1));
    float2 aR01 = __half22float2(*reinterpret_cast<__half2*>(&au2));
    float2 aR23 = __half22float2(*reinterpret_cast<__half2*>(&au3));
    float2 bL01 = __half22float2(*reinterpret_cast<__half2*>(&b0.x));
    float2 bL23 = __half22float2(*reinterpret_cast<__half2*>(&b0.y));
    float2 bR01 = __half22float2(*reinterpret_cast<__half2*>(&b1.x));
    float2 bR23 = __half22float2(*reinterpret_cast<__half2*>(&b1.y));

    float invL = 1.0f / ((aL23.y + bL23.y) + 1e-7f);
    float invR = 1.0f / ((aR23.y + bR23.y) + 1e-7f);

    size_t o = (size_t)(b * 3) * HW + rem;
    *reinterpret_cast<float2*>(out + o)          = make_float2((aL01.x + bL01.x) * invL, (aR01.x + bR01.x) * invR);
    *reinterpret_cast<float2*>(out + o + HW)     = make_float2((aL01.y + bL01.y) * invL, (aR01.y + bR01.y) * invR);
    *reinterpret_cast<float2*>(out + o + 2 * HW) = make_float2((aL23.x + bL23.x) * invL, (aR23.x + bR23.x) * invR);
}

extern "C" void kernel_launch(void* const* d_in, const int* in_sizes, int n_in,
                              void* d_out, int out_size) {
    // Identify inputs by element count — robust to any metadata ordering.
    const float* tenIn     = nullptr;
    const float* tenFlow   = nullptr;
    const float* tenMetric = nullptr;
    for (int i = 0; i < n_in; i++) {
        if      (in_sizes[i] == SZ_IN)     tenIn     = (const float*)d_in[i];
        else if (in_sizes[i] == SZ_FLOW)   tenFlow   = (const float*)d_in[i];
        else if (in_sizes[i] == SZ_METRIC) tenMetric = (const float*)d_in[i];
    }
    float* out = (float*)d_out;

    const int threads = 256;
    const int zblocks = (ZA16 + ZB16 + threads - 1) / threads;  // ~8130
    const int sblocks = (HW + threads - 1) / threads;           // 8100
    const int nblocks = (HW / 2 + threads - 1) / threads;       // 4050

    // Per-batch pipeline, each phase in its individually-fastest form:
    // zero (pure stores) -> splat (msg-floor REDs into L2-hot slice) ->
    // norm (pure reads + output stores).
    for (int b = 0; b < NB; b++) {
        zero_kernel <<<zblocks, threads>>>(b);
        splat_kernel<<<sblocks, threads>>>(tenIn, tenFlow, tenMetric, b);
        norm_kernel <<<nblocks, threads>>>(out, b);
    }
}

// round 14
// speedup vs baseline: 3.1536x; 1.0046x over previous
#include <cuda_runtime.h>
#include <cuda_fp16.h>
#include <cuda_bf16.h>
#include <math.h>

// Problem dims (fixed by the dataset)
#define NB 4
#define CH 3
#define HH 1080
#define WW 1920
#define HW (HH * WW)
#define NHW (NB * HW)

#define SZ_IN     (NB * 3 * HW)   // 24883200
#define SZ_FLOW   (NB * 2 * HW)   // 16588800
#define SZ_METRIC (NB * 1 * HW)   //  8294400

// Staggered dual accumulator, f16, 4 channels (c0*mw, c1*mw, c2*mw, m*w):
//   A_b: [H, W, 4]     — pairs starting at EVEN x0 (cols x0, x0+1)
//   B_b: [H, 1922, 4]  — shifted one col (index x+1, pads both ends) —
//                        pairs starting at ODD x0 (16B-aligned there).
// One 16B v4.f16x2 RED per footprint row: 2 msgs/px (the message floor).
// Batch-major layout [A_0|B_0|A_1|B_1|...]: each batch's 33.2MB slice is
// CONTIGUOUS (fast grid-stride zero) and L2-resident through its
// zero -> splat -> norm window.
#define BW 1922
#define A_B_HALVES ((size_t)HH * WW * 4)              // per-batch A (halves)
#define B_B_HALVES ((size_t)HH * BW * 4)              // per-batch B (halves)
#define AB_HALVES  (A_B_HALVES + B_B_HALVES)          // per-batch total
#define TOT_HALVES ((size_t)NB * AB_HALVES)

__device__ __align__(16) __half g_acc[TOT_HALVES];

static __device__ __forceinline__ unsigned pack2(float a, float b) {
    __half2 h = __floats2half2_rn(a, b);
    return *reinterpret_cast<unsigned*>(&h);
}

// Grid-stride zero of batch b's contiguous A+B slice. 16B stores, several
// per thread — amortizes launch/issue overhead vs 1-store-per-thread.
#define Z16 (AB_HALVES / 8)   // number of 16B chunks per batch slice
__global__ void zero_kernel(int b) {
    float4* p = reinterpret_cast<float4*>(g_acc + (size_t)b * AB_HALVES);
    const float4 z = make_float4(0.f, 0.f, 0.f, 0.f);
    size_t stride = (size_t)gridDim.x * blockDim.x;
    for (size_t i = (size_t)blockIdx.x * blockDim.x + threadIdx.x; i < Z16; i += stride)
        p[i] = z;
}

__global__ void splat_kernel(const float* __restrict__ in,
                             const float* __restrict__ flow,
                             const float* __restrict__ metric,
                             int b) {
    int rem = blockIdx.x * blockDim.x + threadIdx.x;
    if (rem >= HW) return;
    int y = rem / WW;
    int x = rem - y * WW;

    float fx = flow[(size_t)(b * 2 + 0) * HW + rem];
    float fy = flow[(size_t)(b * 2 + 1) * HW + rem];
    float tx = (float)x + fx;
    float ty = (float)y + fy;
    if (!isfinite(tx) || !isfinite(ty)) return;  // ref zeroes these contributions

    float m  = __expf(metric[(size_t)b * HW + rem]);
    float v0 = in[(size_t)(b * 3 + 0) * HW + rem] * m;
    float v1 = in[(size_t)(b * 3 + 1) * HW + rem] * m;
    float v2 = in[(size_t)(b * 3 + 2) * HW + rem] * m;

    float fxf = floorf(tx);
    float fyf = floorf(ty);
    int x0 = (int)fxf;
    int y0 = (int)fyf;
    float ax = tx - fxf;
    float ay = ty - fyf;

    float wx0 = 1.f - ax, wx1 = ax;
    float wy_[2] = {1.f - ay, ay};

    bool odd = (x0 & 1) != 0;
    // even: pair valid iff x0 in [0, WW-2]; odd: iff x0 in [-1, WW-1]
    bool ok = odd ? (x0 >= -1 && x0 <= WW - 1) : ((unsigned)x0 <= (unsigned)(WW - 2));
    if (!ok) return;

    __half* slice = g_acc + (size_t)b * AB_HALVES;
    __half* arr;
    int col, rw;
    if (odd) { arr = slice + A_B_HALVES; col = x0 + 1; rw = BW; }
    else     { arr = slice;              col = x0;     rw = WW; }

#pragma unroll
    for (int dy = 0; dy < 2; dy++) {
        int iy = y0 + dy;
        if (iy < 0 || iy >= HH) continue;
        float W0 = wx0 * wy_[dy];
        float W1 = wx1 * wy_[dy];
        unsigned a0 = pack2(v0 * W0, v1 * W0);
        unsigned a1 = pack2(v2 * W0, m  * W0);
        unsigned b0 = pack2(v0 * W1, v1 * W1);
        unsigned b1 = pack2(v2 * W1, m  * W1);
        __half* ptr = arr + ((size_t)iy * rw + col) * 4;
        asm volatile(
            "red.global.add.noftz.v4.f16x2 [%0], {%1, %2, %3, %4};"
            :: "l"(ptr), "r"(a0), "r"(a1), "r"(b0), "r"(b1)
            : "memory");
    }
}

// Read-only normalize, 4 px/thread (x..x+3, x % 4 == 0):
//   A cells x..x+3   : two 16B loads
//   B cells x+1..x+4 : 8B + 16B + 8B loads
//   outputs          : three float4 plane stores
__global__ void norm_kernel(float* __restrict__ out, int b) {
    int t = blockIdx.x * blockDim.x + threadIdx.x;
    if (t >= HW / 4) return;
    int rem = t * 4;
    int y   = rem / WW;
    int x   = rem - y * WW;

    const __half* A_b = g_acc + (size_t)b * AB_HALVES;
    const __half* B_b = A_b + A_B_HALVES;

    const __half* aRow = A_b + ((size_t)y * WW + x) * 4;
    const __half* bRow = B_b + ((size_t)y * BW + x) * 4;

    float4 aLo = *reinterpret_cast<const float4*>(aRow);       // cells x, x+1
    float4 aHi = *reinterpret_cast<const float4*>(aRow + 8);   // cells x+2, x+3
    uint2  bA  = *reinterpret_cast<const uint2*>(bRow + 4);    // cell  x+1
    float4 bM  = *reinterpret_cast<const float4*>(bRow + 8);   // cells x+2, x+3
    uint2  bZ  = *reinterpret_cast<const uint2*>(bRow + 16);   // cell  x+4

    float o0[4], o1[4], o2[4];

#pragma unroll
    for (int j = 0; j < 4; j++) {
        unsigned a_lo, a_hi, b_lo, b_hi;
        if (j == 0)      { a_lo = __float_as_uint(aLo.x); a_hi = __float_as_uint(aLo.y);
                           b_lo = bA.x;                   b_hi = bA.y; }
        else if (j == 1) { a_lo = __float_as_uint(aLo.z); a_hi = __float_as_uint(aLo.w);
                           b_lo = __float_as_uint(bM.x);  b_hi = __float_as_uint(bM.y); }
        else if (j == 2) { a_lo = __float_as_uint(aHi.x); a_hi = __float_as_uint(aHi.y);
                           b_lo = __float_as_uint(bM.z);  b_hi = __float_as_uint(bM.w); }
        else             { a_lo = __float_as_uint(aHi.z); a_hi = __float_as_uint(aHi.w);
                           b_lo = bZ.x;                   b_hi = bZ.y; }

        float2 a01 = __half22float2(*reinterpret_cast<__half2*>(&a_lo));
        float2 a23 = __half22float2(*reinterpret_cast<__half2*>(&a_hi));
        float2 b01 = __half22float2(*reinterpret_cast<__half2*>(&b_lo));
        float2 b23 = __half22float2(*reinterpret_cast<__half2*>(&b_hi));

        float inv = 1.0f / ((a23.y + b23.y) + 1e-7f);
        o0[j] = (a01.x + b01.x) * inv;
        o1[j] = (a01.y + b01.y) * inv;
        o2[j] = (a23.x + b23.x) * inv;
    }

    size_t o = (size_t)(b * 3) * HW + rem;
    *reinterpret_cast<float4*>(out + o)          = make_float4(o0[0], o0[1], o0[2], o0[3]);
    *reinterpret_cast<float4*>(out + o + HW)     = make_float4(o1[0], o1[1], o1[2], o1[3]);
    *reinterpret_cast<float4*>(out + o + 2 * HW) = make_float4(o2[0], o2[1], o2[2], o2[3]);
}

extern "C" void kernel_launch(void* const* d_in, const int* in_sizes, int n_in,
                              void* d_out, int out_size) {
    // Identify inputs by element count — robust to any metadata ordering.
    const float* tenIn     = nullptr;
    const float* tenFlow   = nullptr;
    const float* tenMetric = nullptr;
    for (int i = 0; i < n_in; i++) {
        if      (in_sizes[i] == SZ_IN)     tenIn     = (const float*)d_in[i];
        else if (in_sizes[i] == SZ_FLOW)   tenFlow   = (const float*)d_in[i];
        else if (in_sizes[i] == SZ_METRIC) tenMetric = (const float*)d_in[i];
    }
    float* out = (float*)d_out;

    const int threads = 256;
    const int zblocks = 148 * 6;                            // grid-stride zero
    const int sblocks = (HW + threads - 1) / threads;       // 8100
    const int nblocks = (HW / 4 + threads - 1) / threads;   // 2025

    for (int b = 0; b < NB; b++) {
        zero_kernel <<<zblocks, threads>>>(b);
        splat_kernel<<<sblocks, threads>>>(tenIn, tenFlow, tenMetric, b);
        norm_kernel <<<nblocks, threads>>>(out, b);
    }
}